// round 14
// baseline (speedup 1.0000x reference)
#include <cuda_runtime.h>

#define N_IN  1024
#define N_OUT 512
#define BATCH 128
#define M     (N_IN + 1)    // 1025 word lines (weights + bias row)
#define TJ    8             // j-columns per block
#define NCH   24            // i-chunks -> grid 64*24 = 1536 blocks, one wave (cap ~1776)
#define NJT   (N_OUT / TJ)  // 64 j-tiles
#define NI_MAX 43           // max rows per chunk (1025/24 -> 42 or 43)

// ---- device scratch (no allocations allowed) ----
__device__ unsigned g_maxbits;        // bitwise max of |weights|; monotone, idempotent across replays
__device__ float2   g_LS[M * BATCH];  // {lr, sign} transposed [i][b]

__device__ __forceinline__ float ex2f_(float x) {
    float r; asm("ex2.approx.ftz.f32 %0, %1;" : "=f"(r) : "f"(x)); return r;
}
__device__ __forceinline__ float lg2f_(float x) {
    float r; asm("lg2.approx.ftz.f32 %0, %1;" : "=f"(r) : "f"(x)); return r;
}

// exp2 on the FMA/ALU pipes (no MUFU): round-to-nearest split via the 1.5*2^23 magic,
// degree-5 polynomial on f in [-0.5, 0.5] (rel err ~2e-6), exponent reinserted by bit-add.
// Clamp at -126 handles tiny |x| and the x==0 (-inf) lane (result ~0, sign term kills it).
__device__ __forceinline__ float ex2poly_(float y) {
    y = fmaxf(y, -126.0f);
    float t = y + 12582912.0f;                 // n = round(y) in low mantissa bits
    int   nb = __float_as_int(t) - 0x4B400000; // = n
    float f = y - (t - 12582912.0f);           // f in [-0.5, 0.5]
    float e = 0.0013333558f;
    e = fmaf(e, f, 0.0096181291f);
    e = fmaf(e, f, 0.0555041087f);
    e = fmaf(e, f, 0.2402265069f);
    e = fmaf(e, f, 0.6931471806f);
    e = fmaf(e, f, 1.0f);
    return __int_as_float(__float_as_int(e) + (nb << 23));
}

// K0: three independent jobs in one launch (proven since R10).
__global__ void __launch_bounds__(256) k_prep(const float* __restrict__ wp,
                                              const float* __restrict__ wn,
                                              const float* __restrict__ x,
                                              float* __restrict__ out) {
    __shared__ float2 sm[32][33];
    const int tid  = threadIdx.x;
    const int gtid = blockIdx.x * 256 + tid;          // 0 .. 65535 (grid = 256 blocks)

    // (a) max scan: wp and wn each 128K float4; 2 strides x 65536 threads
    {
        const float4* wp4 = reinterpret_cast<const float4*>(wp);
        const float4* wn4 = reinterpret_cast<const float4*>(wn);
        float mx = 0.5f;
        #pragma unroll
        for (int s = 0; s < 2; ++s) {
            int idx = s * 65536 + gtid;
            float4 a = wp4[idx], c = wn4[idx];
            mx = fmaxf(mx, fmaxf(fmaxf(fabsf(a.x), fabsf(a.y)), fmaxf(fabsf(a.z), fabsf(a.w))));
            mx = fmaxf(mx, fmaxf(fmaxf(fabsf(c.x), fabsf(c.y)), fmaxf(fabsf(c.z), fabsf(c.w))));
        }
        #pragma unroll
        for (int o = 16; o; o >>= 1)
            mx = fmaxf(mx, __shfl_xor_sync(0xFFFFFFFFu, mx, o));
        if ((tid & 31) == 0)
            atomicMax(&g_maxbits, __float_as_uint(mx));
    }

    // (b) zero output: 16K float4
    if (gtid < (BATCH * N_OUT) / 4)
        reinterpret_cast<float4*>(out)[gtid] = make_float4(0.f, 0.f, 0.f, 0.f);

    // (c) LS transpose: blocks 0..127 each handle a 32i x 32b tile of x
    if (blockIdx.x < 128) {
        const int it = blockIdx.x >> 2;          // 0..31  (i-tile)
        const int bt = blockIdx.x & 3;           // 0..3   (b-tile)
        const int i0 = it * 32, b0 = bt * 32;
        const int tx = tid & 31, tz = tid >> 5;  // tz = 0..7

        #pragma unroll
        for (int r = 0; r < 4; ++r) {            // read coalesced over i
            int bl = tz + r * 8;
            float xv = x[(b0 + bl) * N_IN + i0 + tx];
            float lr = lg2f_(fabsf(xv)) + 1.0f;  // log2(2|x|); -inf at 0 -> ex2 -> 0, s==0 kills term
            float s  = (xv > 0.0f) ? 1.0f : ((xv < 0.0f) ? -1.0f : 0.0f);
            sm[bl][tx] = make_float2(lr, s);
        }
        __syncthreads();
        #pragma unroll
        for (int r = 0; r < 4; ++r) {            // write coalesced over b
            int il = tz + r * 8;
            g_LS[(i0 + il) * BATCH + b0 + tx] = sm[tx][il];
        }
    } else if (blockIdx.x == 128 && tid < BATCH) {
        g_LS[N_IN * BATCH + tid] = make_float2(1.0f, 1.0f);   // bias line: x == 1
    }
}

// One (i,b) pair against TJ=8 columns. qq at jj==1 and jj==5 goes through the
// FMA-pipe poly (14 MUFU ops/row instead of 16). With occ ~52% (NCH=24) the poly's
// dependency chain is covered by eligible warps — retry of the R12 experiment
// under the occupancy that R13 established.
__device__ __forceinline__ void pair8_(const float4* __restrict__ sProw,
                                       float2 l, float* __restrict__ acc) {
    #pragma unroll
    for (int jj = 0; jj < TJ; ++jj) {
        float4 p = sProw[jj];                    // smem broadcast
        float pp = ex2f_(p.z * l.x);             // ratio^Ep (MUFU)
        float qq = (jj == 1 || jj == 5) ? ex2poly_(p.w * l.x)   // FMA pipe
                                        : ex2f_(p.w * l.x);     // MUFU
        acc[jj] = fmaf(l.y, fmaf(p.x, pp, p.y * qq), acc[jj]);
    }
}

// K1: main. Block = 128 threads (all b), TJ=8, NCH=24 (1536 blocks, occ ~52%).
// Params folded at fill: Cp = 0.5*(wp+off), Cn = -0.5*(wn+off), E = log2(2.8+0.2*z).
// ls streamed through a 4-deep register double-buffer (prefetch distance 4 i-iters).
__global__ void __launch_bounds__(128) k_main(const float* __restrict__ wp,
                                              const float* __restrict__ wn,
                                              const float* __restrict__ bp,
                                              const float* __restrict__ bn,
                                              const float* __restrict__ noise,
                                              float* __restrict__ out) {
    __shared__ float4 sP[NI_MAX * TJ];           // 43*8*16B = 5.5 KB

    const int jt = blockIdx.x;                   // 0..63
    const int ch = blockIdx.y;                   // 0..23
    const int j0 = jt * TJ;
    const int i0 = (ch * M) / NCH;
    const int i1 = ((ch + 1) * M) / NCH;
    const int ni = i1 - i0;                      // 42 or 43
    const int b  = threadIdx.x;

    const float off = 0.25f * __uint_as_float(g_maxbits);

    for (int t = b; t < ni * TJ; t += 128) {
        int ii = t >> 3, jj = t & (TJ - 1);
        int i = i0 + ii, j = j0 + jj;
        float wpv = (i < N_IN) ? wp[i * N_OUT + j] : bp[j];
        float wnv = (i < N_IN) ? wn[i * N_OUT + j] : bn[j];
        float2 z = reinterpret_cast<const float2*>(noise)[i * N_OUT + j]; // cols (2j,2j+1), row i
        float4 P;
        P.x =  0.5f * (wpv + off);
        P.y = -0.5f * (wnv + off);
        P.z = lg2f_(2.8f + 0.2f * z.x);
        P.w = lg2f_(2.8f + 0.2f * z.y);
        sP[t] = P;
    }
    __syncthreads();

    float acc[TJ];
    #pragma unroll
    for (int jj = 0; jj < TJ; ++jj) acc[jj] = 0.0f;

    const float2* __restrict__ lsp = &g_LS[i0 * BATCH + b];
    const int last = ni - 1;

    float2 A[4], B[4];
    #pragma unroll
    for (int k = 0; k < 4; ++k) A[k] = lsp[k * BATCH];

    // 10 sub-blocks of 4 (i-local 0..39); unroll-by-2 over sub-blocks
    for (int sb = 0; sb < 10; sb += 2) {
        int base1 = (sb + 1) * 4;
        #pragma unroll
        for (int k = 0; k < 4; ++k) {
            int idx = base1 + k; idx = (idx < ni) ? idx : last;
            B[k] = lsp[idx * BATCH];
        }
        #pragma unroll
        for (int k = 0; k < 4; ++k)
            pair8_(&sP[(sb * 4 + k) * TJ], A[k], acc);

        int base2 = (sb + 2) * 4;
        #pragma unroll
        for (int k = 0; k < 4; ++k) {
            int idx = base2 + k; idx = (idx < ni) ? idx : last;
            A[k] = lsp[idx * BATCH];
        }
        #pragma unroll
        for (int k = 0; k < 4; ++k)
            pair8_(&sP[((sb + 1) * 4 + k) * TJ], B[k], acc);
    }
    // tail: i-local 40 .. ni-1 (A holds idx 40..43 clamped; uniform per block)
    #pragma unroll
    for (int k = 0; k < 3; ++k) {
        if (40 + k < ni)
            pair8_(&sP[(40 + k) * TJ], A[k], acc);
    }

    #pragma unroll
    for (int jj = 0; jj < TJ; ++jj)
        atomicAdd(&out[b * N_OUT + j0 + jj], acc[jj]);   // RED.F32, spread addresses

}

extern "C" void kernel_launch(void* const* d_in, const int* in_sizes, int n_in,
                              void* d_out, int out_size) {
    const float* x     = (const float*)d_in[0];   // (128, 1024)
    const float* w_pos = (const float*)d_in[1];   // (1024, 512)
    const float* w_neg = (const float*)d_in[2];   // (1024, 512)
    const float* b_pos = (const float*)d_in[3];   // (512,)
    const float* b_neg = (const float*)d_in[4];   // (512,)
    const float* noise = (const float*)d_in[5];   // (1025, 1024)
    float* out = (float*)d_out;                   // (128, 512)

    k_prep<<<256, 256>>>(w_pos, w_neg, x, out);
    dim3 grid(NJT, NCH);
    k_main<<<grid, 128>>>(w_pos, w_neg, b_pos, b_neg, noise, out);
}

// round 15
// speedup vs baseline: 1.1038x; 1.1038x over previous
#include <cuda_runtime.h>

#define N_IN  1024
#define N_OUT 512
#define BATCH 128
#define M     (N_IN + 1)    // 1025 word lines (weights + bias row)
#define TJ    8             // j-columns per block
#define NCH   16            // i-chunks -> grid 64*16 = 1024 blocks = one wave
#define NJT   (N_OUT / TJ)  // 64 j-tiles
#define NI_MAX 65           // max rows per chunk

// ---- device scratch (no allocations allowed) ----
__device__ unsigned g_maxbits;        // bitwise max of |weights|; monotone, idempotent across replays
__device__ float2   g_LS[M * BATCH];  // {lr, sign} transposed [i][b]

__device__ __forceinline__ float ex2f_(float x) {
    float r; asm("ex2.approx.ftz.f32 %0, %1;" : "=f"(r) : "f"(x)); return r;
}
__device__ __forceinline__ float lg2f_(float x) {
    float r; asm("lg2.approx.ftz.f32 %0, %1;" : "=f"(r) : "f"(x)); return r;
}

// K0: three independent jobs in one launch.
// (a) max|w| with high MLP (bias 0.5 seeded; atomicMax on non-negative float bits is exact);
// (b) zero d_out (poisoned; k_main REDs into it);
// (c) LS = {1+log2|x|, sign(x)} transposed to [i][b] via 32x32 smem tiles.
__global__ void __launch_bounds__(256) k_prep(const float* __restrict__ wp,
                                              const float* __restrict__ wn,
                                              const float* __restrict__ x,
                                              float* __restrict__ out) {
    __shared__ float2 sm[32][33];
    const int tid  = threadIdx.x;
    const int gtid = blockIdx.x * 256 + tid;          // 0 .. 65535 (grid = 256 blocks)

    // (a) max scan: wp and wn each 128K float4; 2 strides x 65536 threads
    {
        const float4* wp4 = reinterpret_cast<const float4*>(wp);
        const float4* wn4 = reinterpret_cast<const float4*>(wn);
        float mx = 0.5f;
        #pragma unroll
        for (int s = 0; s < 2; ++s) {
            int idx = s * 65536 + gtid;
            float4 a = wp4[idx], c = wn4[idx];
            mx = fmaxf(mx, fmaxf(fmaxf(fabsf(a.x), fabsf(a.y)), fmaxf(fabsf(a.z), fabsf(a.w))));
            mx = fmaxf(mx, fmaxf(fmaxf(fabsf(c.x), fabsf(c.y)), fmaxf(fabsf(c.z), fabsf(c.w))));
        }
        #pragma unroll
        for (int o = 16; o; o >>= 1)
            mx = fmaxf(mx, __shfl_xor_sync(0xFFFFFFFFu, mx, o));
        if ((tid & 31) == 0)
            atomicMax(&g_maxbits, __float_as_uint(mx));
    }

    // (b) zero output: 16K float4
    if (gtid < (BATCH * N_OUT) / 4)
        reinterpret_cast<float4*>(out)[gtid] = make_float4(0.f, 0.f, 0.f, 0.f);

    // (c) LS transpose: blocks 0..127 each handle a 32i x 32b tile of x
    if (blockIdx.x < 128) {
        const int it = blockIdx.x >> 2;          // 0..31  (i-tile)
        const int bt = blockIdx.x & 3;           // 0..3   (b-tile)
        const int i0 = it * 32, b0 = bt * 32;
        const int tx = tid & 31, tz = tid >> 5;  // tz = 0..7

        #pragma unroll
        for (int r = 0; r < 4; ++r) {            // read coalesced over i
            int bl = tz + r * 8;
            float xv = x[(b0 + bl) * N_IN + i0 + tx];
            float lr = lg2f_(fabsf(xv)) + 1.0f;  // log2(2|x|); -inf at 0 -> ex2 -> 0, s==0 kills term
            float s  = (xv > 0.0f) ? 1.0f : ((xv < 0.0f) ? -1.0f : 0.0f);
            sm[bl][tx] = make_float2(lr, s);
        }
        __syncthreads();
        #pragma unroll
        for (int r = 0; r < 4; ++r) {            // write coalesced over b
            int il = tz + r * 8;
            g_LS[(i0 + il) * BATCH + b0 + tx] = sm[tx][il];
        }
    } else if (blockIdx.x == 128 && tid < BATCH) {
        g_LS[N_IN * BATCH + tid] = make_float2(1.0f, 1.0f);   // bias line: x == 1
    }
}

// One (i,b) pair against TJ=8 columns from the smem tile (pure MUFU — the proven form).
__device__ __forceinline__ void pair8_(const float4* __restrict__ sProw,
                                       float2 l, float* __restrict__ acc) {
    #pragma unroll
    for (int jj = 0; jj < TJ; ++jj) {
        float4 p = sProw[jj];                    // smem broadcast
        float pp = ex2f_(p.z * l.x);             // ratio^Ep
        float qq = ex2f_(p.w * l.x);             // ratio^En
        acc[jj] = fmaf(l.y, fmaf(p.x, pp, p.y * qq), acc[jj]);
    }
}

// K1: main. Block = 128 threads (all b), TJ=8, NCH=16 (1024 blocks = one wave).
// Params folded at fill: Cp = 0.5*(wp+off), Cn = -0.5*(wn+off), E = log2(2.8+0.2*z).
// ls streamed through a 4-deep register double-buffer (prefetch distance 4 i-iters
// > L2 latency), sb-loop unrolled x2 so buffer selection is compile-time.
// Chunk sizes: ni = 64 (ch 0..14) or 65 (ch 15) -> 16 sub-blocks of 4 + clamped tail.
__global__ void __launch_bounds__(128) k_main(const float* __restrict__ wp,
                                              const float* __restrict__ wn,
                                              const float* __restrict__ bp,
                                              const float* __restrict__ bn,
                                              const float* __restrict__ noise,
                                              float* __restrict__ out) {
    __shared__ float4 sP[NI_MAX * TJ];           // 65*8*16B = 8.3 KB

    const int jt = blockIdx.x;                   // 0..63
    const int ch = blockIdx.y;                   // 0..15
    const int j0 = jt * TJ;
    const int i0 = (ch * M) / NCH;
    const int i1 = ((ch + 1) * M) / NCH;
    const int ni = i1 - i0;                      // 64 or 65
    const int b  = threadIdx.x;

    const float off = 0.25f * __uint_as_float(g_maxbits);

    for (int t = b; t < ni * TJ; t += 128) {
        int ii = t >> 3, jj = t & (TJ - 1);
        int i = i0 + ii, j = j0 + jj;
        float wpv = (i < N_IN) ? wp[i * N_OUT + j] : bp[j];
        float wnv = (i < N_IN) ? wn[i * N_OUT + j] : bn[j];
        float2 z = reinterpret_cast<const float2*>(noise)[i * N_OUT + j]; // cols (2j,2j+1), row i
        float4 P;
        P.x =  0.5f * (wpv + off);
        P.y = -0.5f * (wnv + off);
        P.z = lg2f_(2.8f + 0.2f * z.x);
        P.w = lg2f_(2.8f + 0.2f * z.y);
        sP[t] = P;
    }
    __syncthreads();

    float acc[TJ];
    #pragma unroll
    for (int jj = 0; jj < TJ; ++jj) acc[jj] = 0.0f;

    const float2* __restrict__ lsp = &g_LS[i0 * BATCH + b];
    const int last = ni - 1;

    float2 A[4], B[4];
    #pragma unroll
    for (int k = 0; k < 4; ++k) A[k] = lsp[k * BATCH];

    // 16 sub-blocks of 4 (covers i-local 0..63); unroll-by-2 over sub-blocks
    for (int sb = 0; sb < 16; sb += 2) {
        int base1 = (sb + 1) * 4;
        #pragma unroll
        for (int k = 0; k < 4; ++k) {
            int idx = base1 + k; idx = (idx < ni) ? idx : last;
            B[k] = lsp[idx * BATCH];
        }
        #pragma unroll
        for (int k = 0; k < 4; ++k)
            pair8_(&sP[(sb * 4 + k) * TJ], A[k], acc);

        int base2 = (sb + 2) * 4;
        #pragma unroll
        for (int k = 0; k < 4; ++k) {
            int idx = base2 + k; idx = (idx < ni) ? idx : last;
            A[k] = lsp[idx * BATCH];
        }
        #pragma unroll
        for (int k = 0; k < 4; ++k)
            pair8_(&sP[((sb + 1) * 4 + k) * TJ], B[k], acc);
    }
    // tail: i-local 64 when ni == 65 (A[0] holds the clamped last element)
    if (ni > 64)
        pair8_(&sP[64 * TJ], A[0], acc);

    #pragma unroll
    for (int jj = 0; jj < TJ; ++jj)
        atomicAdd(&out[b * N_OUT + j0 + jj], acc[jj]);   // RED.F32, spread addresses
}

extern "C" void kernel_launch(void* const* d_in, const int* in_sizes, int n_in,
                              void* d_out, int out_size) {
    const float* x     = (const float*)d_in[0];   // (128, 1024)
    const float* w_pos = (const float*)d_in[1];   // (1024, 512)
    const float* w_neg = (const float*)d_in[2];   // (1024, 512)
    const float* b_pos = (const float*)d_in[3];   // (512,)
    const float* b_neg = (const float*)d_in[4];   // (512,)
    const float* noise = (const float*)d_in[5];   // (1025, 1024)
    float* out = (float*)d_out;                   // (128, 512)

    k_prep<<<256, 256>>>(w_pos, w_neg, x, out);
    dim3 grid(NJT, NCH);
    k_main<<<grid, 128>>>(w_pos, w_neg, b_pos, b_neg, noise, out);
}

// round 16
// speedup vs baseline: 1.1114x; 1.0069x over previous
#include <cuda_runtime.h>

#define N_IN  1024
#define N_OUT 512
#define BATCH 128
#define M     (N_IN + 1)    // 1025 word lines (weights + bias row)
#define TJ    8             // j-columns per block
#define NCH   16            // i-chunks -> grid 64*16 = 1024 blocks = one wave
#define NJT   (N_OUT / TJ)  // 64 j-tiles
#define NI_MAX 65           // max rows per chunk

// ---- device scratch (no allocations allowed) ----
__device__ unsigned g_maxbits;        // bitwise max of |weights|; monotone, idempotent across replays
__device__ float2   g_LS[M * BATCH];  // {lr, sign} transposed [i][b]

__device__ __forceinline__ float ex2f_(float x) {
    float r; asm("ex2.approx.ftz.f32 %0, %1;" : "=f"(r) : "f"(x)); return r;
}
__device__ __forceinline__ float lg2f_(float x) {
    float r; asm("lg2.approx.ftz.f32 %0, %1;" : "=f"(r) : "f"(x)); return r;
}

// K0: three independent jobs in one launch.
// (a) max|w| with high MLP (bias 0.5 seeded; atomicMax on non-negative float bits is exact);
// (b) zero d_out (poisoned; k_main REDs into it);
// (c) LS = {1+log2|x|, sign(x)} transposed to [i][b] via 32x32 smem tiles.
__global__ void __launch_bounds__(256) k_prep(const float* __restrict__ wp,
                                              const float* __restrict__ wn,
                                              const float* __restrict__ x,
                                              float* __restrict__ out) {
    __shared__ float2 sm[32][33];
    const int tid  = threadIdx.x;
    const int gtid = blockIdx.x * 256 + tid;          // 0 .. 65535 (grid = 256 blocks)

    // (a) max scan: wp and wn each 128K float4; 2 strides x 65536 threads
    {
        const float4* wp4 = reinterpret_cast<const float4*>(wp);
        const float4* wn4 = reinterpret_cast<const float4*>(wn);
        float mx = 0.5f;
        #pragma unroll
        for (int s = 0; s < 2; ++s) {
            int idx = s * 65536 + gtid;
            float4 a = wp4[idx], c = wn4[idx];
            mx = fmaxf(mx, fmaxf(fmaxf(fabsf(a.x), fabsf(a.y)), fmaxf(fabsf(a.z), fabsf(a.w))));
            mx = fmaxf(mx, fmaxf(fmaxf(fabsf(c.x), fabsf(c.y)), fmaxf(fabsf(c.z), fabsf(c.w))));
        }
        #pragma unroll
        for (int o = 16; o; o >>= 1)
            mx = fmaxf(mx, __shfl_xor_sync(0xFFFFFFFFu, mx, o));
        if ((tid & 31) == 0)
            atomicMax(&g_maxbits, __float_as_uint(mx));
    }

    // (b) zero output: 16K float4
    if (gtid < (BATCH * N_OUT) / 4)
        reinterpret_cast<float4*>(out)[gtid] = make_float4(0.f, 0.f, 0.f, 0.f);

    // (c) LS transpose: blocks 0..127 each handle a 32i x 32b tile of x
    if (blockIdx.x < 128) {
        const int it = blockIdx.x >> 2;          // 0..31  (i-tile)
        const int bt = blockIdx.x & 3;           // 0..3   (b-tile)
        const int i0 = it * 32, b0 = bt * 32;
        const int tx = tid & 31, tz = tid >> 5;  // tz = 0..7

        #pragma unroll
        for (int r = 0; r < 4; ++r) {            // read coalesced over i
            int bl = tz + r * 8;
            float xv = x[(b0 + bl) * N_IN + i0 + tx];
            float lr = lg2f_(fabsf(xv)) + 1.0f;  // log2(2|x|); -inf at 0 -> ex2 -> 0, s==0 kills term
            float s  = (xv > 0.0f) ? 1.0f : ((xv < 0.0f) ? -1.0f : 0.0f);
            sm[bl][tx] = make_float2(lr, s);
        }
        __syncthreads();
        #pragma unroll
        for (int r = 0; r < 4; ++r) {            // write coalesced over b
            int il = tz + r * 8;
            g_LS[(i0 + il) * BATCH + b0 + tx] = sm[tx][il];
        }
    } else if (blockIdx.x == 128 && tid < BATCH) {
        g_LS[N_IN * BATCH + tid] = make_float2(1.0f, 1.0f);   // bias line: x == 1
    }
}

// One (i,b) pair against TJ=8 columns from the smem tile (pure MUFU — the proven form).
__device__ __forceinline__ void pair8_(const float4* __restrict__ sProw,
                                       float2 l, float* __restrict__ acc) {
    #pragma unroll
    for (int jj = 0; jj < TJ; ++jj) {
        float4 p = sProw[jj];                    // smem broadcast
        float pp = ex2f_(p.z * l.x);             // ratio^Ep
        float qq = ex2f_(p.w * l.x);             // ratio^En
        acc[jj] = fmaf(l.y, fmaf(p.x, pp, p.y * qq), acc[jj]);
    }
}

// K1: main. Block = 128 threads (all b), TJ=8, NCH=16 (1024 blocks = one wave).
// Params folded at fill: Cp = 0.5*(wp+off), Cn = -0.5*(wn+off), E = log2(2.8+0.2*z).
// ls streamed through a 4-deep register double-buffer (prefetch distance 4 i-iters
// > L2 latency), sb-loop unrolled x2 so buffer selection is compile-time.
// Chunk sizes: ni = 64 (ch 0..14) or 65 (ch 15) -> 16 sub-blocks of 4 + clamped tail.
__global__ void __launch_bounds__(128) k_main(const float* __restrict__ wp,
                                              const float* __restrict__ wn,
                                              const float* __restrict__ bp,
                                              const float* __restrict__ bn,
                                              const float* __restrict__ noise,
                                              float* __restrict__ out) {
    __shared__ float4 sP[NI_MAX * TJ];           // 65*8*16B = 8.3 KB

    const int jt = blockIdx.x;                   // 0..63
    const int ch = blockIdx.y;                   // 0..15
    const int j0 = jt * TJ;
    const int i0 = (ch * M) / NCH;
    const int i1 = ((ch + 1) * M) / NCH;
    const int ni = i1 - i0;                      // 64 or 65
    const int b  = threadIdx.x;

    const float off = 0.25f * __uint_as_float(g_maxbits);

    for (int t = b; t < ni * TJ; t += 128) {
        int ii = t >> 3, jj = t & (TJ - 1);
        int i = i0 + ii, j = j0 + jj;
        float wpv = (i < N_IN) ? wp[i * N_OUT + j] : bp[j];
        float wnv = (i < N_IN) ? wn[i * N_OUT + j] : bn[j];
        float2 z = reinterpret_cast<const float2*>(noise)[i * N_OUT + j]; // cols (2j,2j+1), row i
        float4 P;
        P.x =  0.5f * (wpv + off);
        P.y = -0.5f * (wnv + off);
        P.z = lg2f_(2.8f + 0.2f * z.x);
        P.w = lg2f_(2.8f + 0.2f * z.y);
        sP[t] = P;
    }
    __syncthreads();

    float acc[TJ];
    #pragma unroll
    for (int jj = 0; jj < TJ; ++jj) acc[jj] = 0.0f;

    const float2* __restrict__ lsp = &g_LS[i0 * BATCH + b];
    const int last = ni - 1;

    float2 A[4], B[4];
    #pragma unroll
    for (int k = 0; k < 4; ++k) A[k] = lsp[k * BATCH];

    // 16 sub-blocks of 4 (covers i-local 0..63); unroll-by-2 over sub-blocks
    for (int sb = 0; sb < 16; sb += 2) {
        int base1 = (sb + 1) * 4;
        #pragma unroll
        for (int k = 0; k < 4; ++k) {
            int idx = base1 + k; idx = (idx < ni) ? idx : last;
            B[k] = lsp[idx * BATCH];
        }
        #pragma unroll
        for (int k = 0; k < 4; ++k)
            pair8_(&sP[(sb * 4 + k) * TJ], A[k], acc);

        int base2 = (sb + 2) * 4;
        #pragma unroll
        for (int k = 0; k < 4; ++k) {
            int idx = base2 + k; idx = (idx < ni) ? idx : last;
            A[k] = lsp[idx * BATCH];
        }
        #pragma unroll
        for (int k = 0; k < 4; ++k)
            pair8_(&sP[((sb + 1) * 4 + k) * TJ], B[k], acc);
    }
    // tail: i-local 64 when ni == 65 (A[0] holds the clamped last element)
    if (ni > 64)
        pair8_(&sP[64 * TJ], A[0], acc);

    #pragma unroll
    for (int jj = 0; jj < TJ; ++jj)
        atomicAdd(&out[b * N_OUT + j0 + jj], acc[jj]);   // RED.F32, spread addresses
}

extern "C" void kernel_launch(void* const* d_in, const int* in_sizes, int n_in,
                              void* d_out, int out_size) {
    const float* x     = (const float*)d_in[0];   // (128, 1024)
    const float* w_pos = (const float*)d_in[1];   // (1024, 512)
    const float* w_neg = (const float*)d_in[2];   // (1024, 512)
    const float* b_pos = (const float*)d_in[3];   // (512,)
    const float* b_neg = (const float*)d_in[4];   // (512,)
    const float* noise = (const float*)d_in[5];   // (1025, 1024)
    float* out = (float*)d_out;                   // (128, 512)

    k_prep<<<256, 256>>>(w_pos, w_neg, x, out);
    dim3 grid(NJT, NCH);
    k_main<<<grid, 128>>>(w_pos, w_neg, b_pos, b_neg, noise, out);
}